// round 6
// baseline (speedup 1.0000x reference)
#include <cuda_runtime.h>
#include <stdint.h>

// ROISelect: per-row top-k(score) + ROI gather, monolithic, sort-free.
// One CTA per row: software-pipelined (double-buffered) float4 streaming scan
// filters score >= 2.72 (~427 candidates/row, 8.3-sigma margin) into shared
// memory, then exact sorted ranks via all-pairs comparison over unique u64
// keys (value | ~index, matching tf.nn.top_k tie order), writing out[rank]
// directly. Exact 12-bit radix-select fallback guarantees correctness if the
// statistical threshold ever misfires (count outside [256, 4096]).

#define B_ROWS 128
#define N_COLS 131072
#define K_TOP  256
#define TPB    1024
#define CAP    4096
#define V4_PER_THREAD (N_COLS / 4 / TPB)   // 32
#define GROUPS 8
#define GSIZE  (V4_PER_THREAD / GROUPS)    // 4 float4 per load group

__device__ __forceinline__ unsigned int f2u(float f) {
    unsigned int b = __float_as_uint(f);
    return (b & 0x80000000u) ? ~b : (b | 0x80000000u);
}
__device__ __forceinline__ float u2f(unsigned int u) {
    unsigned int b = (u & 0x80000000u) ? (u ^ 0x80000000u) : ~u;
    return __uint_as_float(b);
}

__global__ __launch_bounds__(TPB, 1)
void roiselect_kernel(const float* __restrict__ score,
                      const float* __restrict__ roi,
                      float* __restrict__ out_roi,
                      float* __restrict__ out_score)
{
    __shared__ int s_cnt;
    __shared__ int s_bin;
    extern __shared__ unsigned long long cand[];   // CAP entries = 32 KB

    const int tid = threadIdx.x;
    const int row = blockIdx.x;
    const float4* sc4 = (const float4*)(score + (size_t)row * N_COLS);

    if (tid == 0) s_cnt = 0;
    __syncthreads();

    // ---------- Streaming filter: double-buffered groups of 4 LDG.128 ----------
    const float TGUESS = 2.72f;
    float4 buf[2][GSIZE];

    #pragma unroll
    for (int u = 0; u < GSIZE; ++u)                 // prologue: group 0
        buf[0][u] = sc4[tid + u * TPB];

    #pragma unroll
    for (int g = 0; g < GROUPS; ++g) {
        const int cur = g & 1;
        if (g + 1 < GROUPS) {                       // prefetch group g+1
            #pragma unroll
            for (int u = 0; u < GSIZE; ++u)
                buf[cur ^ 1][u] = sc4[tid + ((g + 1) * GSIZE + u) * TPB];
        }
        #pragma unroll
        for (int u = 0; u < GSIZE; ++u) {           // process group g
            int ebase = (tid + (g * GSIZE + u) * TPB) * 4;
            float vals[4] = {buf[cur][u].x, buf[cur][u].y,
                             buf[cur][u].z, buf[cur][u].w};
            #pragma unroll
            for (int c = 0; c < 4; ++c) {
                if (vals[c] >= TGUESS) {
                    int pos = atomicAdd(&s_cnt, 1);
                    if (pos < CAP) {
                        unsigned int uu = __float_as_uint(vals[c]) | 0x80000000u;
                        cand[pos] = ((unsigned long long)uu << 32)
                                  | (unsigned int)~(unsigned int)(ebase + c);
                    }
                }
            }
        }
    }
    __syncthreads();
    unsigned int count = (unsigned int)s_cnt;

    // ---------- Exact fallback: 12-bit radix select (never taken on this data) ----------
    if (count < K_TOP || count > CAP) {
        unsigned int* hist  = (unsigned int*)cand;   // 4096 bins (aliased)
        unsigned int* sdata = hist + 4096;           // 1024 thread sums
        for (int i = tid; i < 4096; i += TPB) hist[i] = 0;
        if (tid == 0) s_cnt = 0;
        __syncthreads();

        for (int i = 0; i < V4_PER_THREAD; ++i) {
            float4 f = sc4[tid + i * TPB];
            float vals[4] = {f.x, f.y, f.z, f.w};
            #pragma unroll
            for (int c = 0; c < 4; ++c)
                atomicAdd(&hist[f2u(vals[c]) >> 20], 1u);
        }
        __syncthreads();

        unsigned int h0 = hist[4*tid+0], h1 = hist[4*tid+1];
        unsigned int h2 = hist[4*tid+2], h3 = hist[4*tid+3];
        sdata[tid] = h0 + h1 + h2 + h3;
        __syncthreads();
        for (int d = 1; d < TPB; d <<= 1) {          // inclusive suffix scan
            unsigned int vv = (tid + d < TPB) ? sdata[tid + d] : 0u;
            __syncthreads();
            sdata[tid] += vv;
            __syncthreads();
        }
        unsigned int Anext = (tid + 1 < TPB) ? sdata[tid + 1] : 0u;
        unsigned int cum3 = Anext + h3;
        unsigned int cum2 = cum3 + h2;
        unsigned int cum1 = cum2 + h1;
        unsigned int cum0 = cum1 + h0;
        if (cum3 >= K_TOP && Anext < K_TOP) s_bin = 4*tid + 3;
        if (cum2 >= K_TOP && cum3  < K_TOP) s_bin = 4*tid + 2;
        if (cum1 >= K_TOP && cum2  < K_TOP) s_bin = 4*tid + 1;
        if (cum0 >= K_TOP && cum1  < K_TOP) s_bin = 4*tid + 0;
        __syncthreads();
        unsigned int uthr = (unsigned int)s_bin << 20;
        __syncthreads();   // uthr read by all; hist region can be overwritten

        for (int i = 0; i < V4_PER_THREAD; ++i) {
            int v4i = tid + i * TPB;
            float4 f = sc4[v4i];
            int ebase = v4i * 4;
            float vals[4] = {f.x, f.y, f.z, f.w};
            #pragma unroll
            for (int c = 0; c < 4; ++c) {
                unsigned int u = f2u(vals[c]);
                if (u >= uthr) {
                    int pos = atomicAdd(&s_cnt, 1);
                    if (pos < CAP)
                        cand[pos] = ((unsigned long long)u << 32)
                                  | (unsigned int)~(unsigned int)(ebase + c);
                }
            }
        }
        __syncthreads();
        count = min((unsigned int)s_cnt, (unsigned int)CAP);
    }

    // Pad to even for the ulonglong2 inner loop (a 0 key never outranks a
    // real key: all real keys have bit 63 set). count==CAP is even, so the
    // pad write never exceeds the buffer.
    if (tid == 0 && (count & 1u)) cand[count] = 0ULL;
    __syncthreads();
    const int half = (int)((count + 1u) >> 1);
    const ulonglong2* c2 = (const ulonglong2*)cand;

    // ---------- Exact rank selection (keys unique via index tie-break) ----------
    for (int c = tid; c < (int)count; c += TPB) {
        unsigned long long key = cand[c];
        int rank = 0;
        #pragma unroll 8
        for (int i = 0; i < half; ++i) {
            ulonglong2 p = c2[i];
            rank += (p.x > key) + (p.y > key);
        }
        if (rank < K_TOP) {
            unsigned int u   = (unsigned int)(key >> 32);
            unsigned int idx = ~(unsigned int)key;
            out_score[row * K_TOP + rank] = u2f(u);
            const float4* r4 = (const float4*)roi;
            ((float4*)out_roi)[row * K_TOP + rank] =
                r4[(size_t)row * N_COLS + idx];
        }
    }
}

extern "C" void kernel_launch(void* const* d_in, const int* in_sizes, int n_in,
                              void* d_out, int out_size) {
    (void)in_sizes; (void)n_in; (void)out_size;
    const float* score = (const float*)d_in[0];
    const float* roi   = (const float*)d_in[1];
    float* out_roi   = (float*)d_out;                               // [128,256,4]
    float* out_score = (float*)d_out + (size_t)B_ROWS * K_TOP * 4;  // [128,256]
    roiselect_kernel<<<B_ROWS, TPB, CAP * sizeof(unsigned long long)>>>(
        score, roi, out_roi, out_score);
}